// round 8
// baseline (speedup 1.0000x reference)
#include <cuda_runtime.h>
#include <cuda_bf16.h>
#include <stdint.h>
#include <math.h>

#define BT    16384
#define DIN   1024
#define DHID  512
#define DCODE 1024
#define KCB   256
#define T3    3072
#define TSEQ  512
#define NB    32

// ---------------- scratch (device globals; allocations are banned) ----------
__device__ float g_h1[(size_t)BT * DHID];
__device__ float g_feat[(size_t)BT * DCODE];
__device__ float g_q[(size_t)BT * DCODE];
__device__ float g_S[(size_t)BT * KCB];
__device__ float g_cbT[(size_t)DCODE * KCB];
__device__ float g_cnorm[KCB];
__device__ float g_p[(size_t)BT * DHID];
__device__ float g_pm[NB * DHID];
__device__ float g_xm[NB * DCODE];
__device__ float g_gx[(size_t)BT * T3];    // reused as recon buffer after GRU
__device__ float g_ctx[(size_t)BT * DCODE];
__device__ float g_hG[2 * NB * DCODE];
__device__ double g_acc[8];   // 0:recon_sse 1:vq_sse 2:xx 3:yy 4:xy
__device__ unsigned g_cnt;
__device__ unsigned g_gen;

// ---------------- small asm helpers -----------------------------------------
__device__ __forceinline__ uint32_t smem_u32(const void* p) {
    uint32_t a;
    asm("{ .reg .u64 t; cvta.to.shared.u64 t, %1; cvt.u32.u64 %0, t; }"
        : "=r"(a) : "l"(p));
    return a;
}

__device__ __forceinline__ void cp16(uint32_t dst, const void* src) {
    asm volatile("{ .reg .u64 g; cvta.to.global.u64 g, %1; "
                 "cp.async.ca.shared.global [%0], [g], 16; }"
                 :: "r"(dst), "l"(src));
}
#define CP_COMMIT() asm volatile("cp.async.commit_group;" ::: "memory")
#define CP_WAIT1()  asm volatile("cp.async.wait_group 1;" ::: "memory")

__device__ __forceinline__ unsigned long long dup2(float x) {
    unsigned long long r;
    asm("mov.b64 %0, {%1, %1};" : "=l"(r) : "f"(x));
    return r;
}
__device__ __forceinline__ void ffma2(unsigned long long& d,
                                      unsigned long long a, unsigned long long b) {
    asm("fma.rn.f32x2 %0, %1, %2, %0;" : "+l"(d) : "l"(a), "l"(b));
}
__device__ __forceinline__ void unpk(unsigned long long v, float& lo, float& hi) {
    asm("mov.b64 {%0, %1}, %2;" : "=f"(lo), "=f"(hi) : "l"(v));
}

// ---------------- block reduce (256 threads) -> atomicAdd double ------------
__device__ __forceinline__ void block_reduce_add(double local, double* dst) {
    __shared__ double sred[8];
    int tid = threadIdx.x;
    #pragma unroll
    for (int o = 16; o; o >>= 1)
        local += __shfl_down_sync(0xffffffffu, local, o);
    if ((tid & 31) == 0) sred[tid >> 5] = local;
    __syncthreads();
    if (tid == 0) {
        double s = 0.0;
        #pragma unroll
        for (int i = 0; i < 8; i++) s += sred[i];
        atomicAdd(dst, s);
    }
}

// ---------------- generic MSE-sum: sum((a-b)^2) -> g_acc[slot] --------------
__global__ void __launch_bounds__(256) mse_kernel(const float* __restrict__ a,
                                                  const float* __restrict__ b,
                                                  size_t n, int slot) {
    double local = 0.0;
    size_t i = (size_t)blockIdx.x * blockDim.x + threadIdx.x;
    size_t stride = (size_t)gridDim.x * blockDim.x;
    for (; i < n; i += stride) {
        double d = (double)a[i] - (double)b[i];
        local += d * d;
    }
    block_reduce_add(local, &g_acc[slot]);
}

// ---------------- f32x2 SGEMM: C = A[M,K]*B[K,N] + bias ---------------------
// 128x128 CTA tile, BK=16, 256 threads, 8x8/thread with f32x2 accumulators,
// 3-stage cp.async pipeline. EPI: 0 = bias+store, 1 = bias+relu+store.
#define LDA   20                 // floats per As row (16 + 4 pad, keeps 16B align)
#define STG_A (128 * LDA)        // 2560 floats
#define STG_B (16 * 128)         // 2048 floats
#define STG_F (STG_A + STG_B)    // 4608 floats / stage
#define SG_SMEM (3 * STG_F * 4)  // 55296 bytes

template <int EPI>
__global__ void __launch_bounds__(256, 2) sgemm2(
    const float* __restrict__ A, const float* __restrict__ B,
    const float* __restrict__ bias, float* __restrict__ C,
    int M, int N, int K)
{
    extern __shared__ float sh[];
    const int tid = threadIdx.x;
    const int bx = blockIdx.x, by = blockIdx.y;
    const int tx = (tid & 15) << 3, ty = (tid >> 4) << 3;
    const int m0 = by * 128, n0 = bx * 128;

    // fill mapping: A -> 2 float4 per thread, B -> 2 float4 per thread
    const int fam = tid >> 1;
    const int faq = (tid & 1) * 2;        // k-quad base
    const int fbk = tid >> 4;
    const int fbn = (tid & 15) * 8;
    const float* Abase = A + (size_t)(m0 + fam) * K;
    const float* Bbase = B + (size_t)fbk * N + n0 + fbn;
    const uint32_t shb = smem_u32(sh);

    unsigned long long acc[8][4];
    #pragma unroll
    for (int i = 0; i < 8; i++)
        #pragma unroll
        for (int j = 0; j < 4; j++) acc[i][j] = 0ull;

    const int NIT = K >> 4;

    // prologue: fill stages 0,1
    #pragma unroll
    for (int s = 0; s < 2; s++) {
        const int kc = s << 4;
        uint32_t as = shb + (uint32_t)((s * STG_F + fam * LDA) * 4);
        cp16(as + (uint32_t)(faq * 16), Abase + kc + faq * 4);
        cp16(as + (uint32_t)((faq + 1) * 16), Abase + kc + (faq + 1) * 4);
        uint32_t bs = shb + (uint32_t)((s * STG_F + STG_A + fbk * 128 + fbn) * 4);
        cp16(bs, Bbase + (size_t)kc * N);
        cp16(bs + 16, Bbase + (size_t)kc * N + 4);
        CP_COMMIT();
    }

    int buf = 0;
    for (int it = 0; it < NIT; it++) {
        CP_WAIT1();
        __syncthreads();

        // prefetch stage it+2 (overlaps with compute below)
        if (it + 2 < NIT) {
            const int s = (it + 2) % 3;
            const int kc = (it + 2) << 4;
            uint32_t as = shb + (uint32_t)((s * STG_F + fam * LDA) * 4);
            cp16(as + (uint32_t)(faq * 16), Abase + kc + faq * 4);
            cp16(as + (uint32_t)((faq + 1) * 16), Abase + kc + (faq + 1) * 4);
            uint32_t bs = shb + (uint32_t)((s * STG_F + STG_A + fbk * 128 + fbn) * 4);
            cp16(bs, Bbase + (size_t)kc * N);
            cp16(bs + 16, Bbase + (size_t)kc * N + 4);
        }
        CP_COMMIT();

        const float* As = sh + buf * STG_F;
        const float* Bs = As + STG_A;

        #pragma unroll
        for (int kp = 0; kp < 16; kp += 2) {
            float2 ra2[8];
            #pragma unroll
            for (int i = 0; i < 8; i++)
                ra2[i] = *(const float2*)&As[(ty + i) * LDA + kp];
            ulonglong2 b0a = *(const ulonglong2*)&Bs[kp * 128 + tx];
            ulonglong2 b0b = *(const ulonglong2*)&Bs[kp * 128 + tx + 4];
            ulonglong2 b1a = *(const ulonglong2*)&Bs[(kp + 1) * 128 + tx];
            ulonglong2 b1b = *(const ulonglong2*)&Bs[(kp + 1) * 128 + tx + 4];
            #pragma unroll
            for (int i = 0; i < 8; i++) {
                unsigned long long a0 = dup2(ra2[i].x);
                ffma2(acc[i][0], a0, b0a.x);
                ffma2(acc[i][1], a0, b0a.y);
                ffma2(acc[i][2], a0, b0b.x);
                ffma2(acc[i][3], a0, b0b.y);
                unsigned long long a1 = dup2(ra2[i].y);
                ffma2(acc[i][0], a1, b1a.x);
                ffma2(acc[i][1], a1, b1a.y);
                ffma2(acc[i][2], a1, b1b.x);
                ffma2(acc[i][3], a1, b1b.y);
            }
        }
        buf = (buf + 1 == 3) ? 0 : buf + 1;
    }

    // epilogue
    float bvs[8];
    #pragma unroll
    for (int j = 0; j < 8; j++) bvs[j] = bias ? bias[n0 + tx + j] : 0.f;

    #pragma unroll
    for (int i = 0; i < 8; i++) {
        float o[8];
        #pragma unroll
        for (int jp = 0; jp < 4; jp++) unpk(acc[i][jp], o[2 * jp], o[2 * jp + 1]);
        #pragma unroll
        for (int j = 0; j < 8; j++) {
            o[j] += bvs[j];
            if (EPI == 1) o[j] = fmaxf(o[j], 0.f);
        }
        float* cp = C + (size_t)(m0 + ty + i) * N + n0 + tx;
        *(float4*)cp = make_float4(o[0], o[1], o[2], o[3]);
        *(float4*)(cp + 4) = make_float4(o[4], o[5], o[6], o[7]);
    }
}

// ---------------- LayerNorm(512) + ReLU in place ----------------------------
__global__ void __launch_bounds__(256) ln_relu(float* __restrict__ h,
                                               const float* __restrict__ gg,
                                               const float* __restrict__ bb)
{
    __shared__ float red[16];
    int tid = threadIdx.x;
    float* r = h + (size_t)blockIdx.x * DHID;
    float v0 = r[tid], v1 = r[tid + 256];
    float s = v0 + v1, q = v0 * v0 + v1 * v1;
    #pragma unroll
    for (int o = 16; o; o >>= 1) {
        s += __shfl_xor_sync(0xffffffffu, s, o);
        q += __shfl_xor_sync(0xffffffffu, q, o);
    }
    if ((tid & 31) == 0) { red[tid >> 5] = s; red[8 + (tid >> 5)] = q; }
    __syncthreads();
    if (tid < 32) {
        float ss = (tid < 8) ? red[tid] : 0.f;
        float qq = (tid < 8) ? red[8 + tid] : 0.f;
        #pragma unroll
        for (int o = 4; o; o >>= 1) {
            ss += __shfl_xor_sync(0xffffffffu, ss, o);
            qq += __shfl_xor_sync(0xffffffffu, qq, o);
        }
        if (tid == 0) { red[0] = ss; red[1] = qq; }
    }
    __syncthreads();
    float mean = red[0] * (1.f / 512.f);
    float var = red[1] * (1.f / 512.f) - mean * mean;
    float rs = rsqrtf(var + 1e-5f);
    r[tid]       = fmaxf((v0 - mean) * rs * gg[tid] + bb[tid], 0.f);
    r[tid + 256] = fmaxf((v1 - mean) * rs * gg[tid + 256] + bb[tid + 256], 0.f);
}

// ---------------- VQ helpers -------------------------------------------------
__global__ void transpose_cb(const float* __restrict__ cb) {
    int d = blockIdx.x, k = threadIdx.x;
    g_cbT[(size_t)d * KCB + k] = cb[(size_t)k * DCODE + d];
}

__global__ void __launch_bounds__(256) cnorm_k(const float* __restrict__ cb) {
    __shared__ float red[8];
    int k = blockIdx.x, tid = threadIdx.x;
    const float* row = cb + (size_t)k * DCODE;
    float s = 0.f;
    for (int d = tid; d < DCODE; d += 256) { float v = row[d]; s += v * v; }
    #pragma unroll
    for (int o = 16; o; o >>= 1) s += __shfl_xor_sync(0xffffffffu, s, o);
    if ((tid & 31) == 0) red[tid >> 5] = s;
    __syncthreads();
    if (tid == 0) {
        float t = 0.f;
        #pragma unroll
        for (int i = 0; i < 8; i++) t += red[i];
        g_cnorm[k] = t;
    }
}

__global__ void __launch_bounds__(256) vq_kernel(const float* __restrict__ cb) {
    __shared__ float sv[256];
    __shared__ int si[256];
    int tok = blockIdx.x, tid = threadIdx.x;
    float v = g_cnorm[tid] - 2.f * g_S[(size_t)tok * KCB + tid];
    sv[tid] = v; si[tid] = tid;
    __syncthreads();
    for (int s = 128; s > 0; s >>= 1) {
        if (tid < s) {
            float v2 = sv[tid + s]; int i2 = si[tid + s];
            if (v2 < sv[tid] || (v2 == sv[tid] && i2 < si[tid])) { sv[tid] = v2; si[tid] = i2; }
        }
        __syncthreads();
    }
    int best = si[0];
    const float* crow = cb + (size_t)best * DCODE;
    float* qrow = g_q + (size_t)tok * DCODE;
    #pragma unroll
    for (int i = 0; i < 4; i++) {
        int d = tid + i * 256;
        qrow[d] = crow[d];
    }
}

// ---------------- projector mean, xm = pm@W2+b2, MMD -------------------------
__global__ void pm_kernel() {
    int id = blockIdx.x * 256 + threadIdx.x;
    int b = id >> 9, d = id & 511;
    const float* p = g_p + (size_t)b * TSEQ * DHID + d;
    float s = 0.f;
    for (int t = 0; t < TSEQ; t++) s += p[(size_t)t * DHID];
    g_pm[id] = s * (1.f / (float)TSEQ);
}

__global__ void __launch_bounds__(256) xm_kernel(const float* __restrict__ W2,
                                                 const float* __restrict__ b2) {
    __shared__ float sp[DHID];
    int b = blockIdx.x;
    int n = blockIdx.y * 256 + threadIdx.x;
    for (int e = threadIdx.x; e < DHID; e += 256) sp[e] = g_pm[b * DHID + e];
    __syncthreads();
    float a = b2[n];
    for (int k = 0; k < DHID; k++) a += sp[k] * W2[(size_t)k * DCODE + n];
    g_xm[b * DCODE + n] = a;
}

__global__ void __launch_bounds__(256) mmd_kernel(const float* __restrict__ prior) {
    int i = blockIdx.x;
    int m = blockIdx.y;
    const float* Arow = ((m == 1) ? prior : g_xm) + (size_t)i * DCODE;
    const float* Bmat = (m == 0) ? g_xm : prior;
    int j = threadIdx.x >> 3, part = threadIdx.x & 7;
    const float* Brow = Bmat + (size_t)j * DCODE;
    float s = 0.f;
    for (int d = part; d < DCODE; d += 8) { float df = Arow[d] - Brow[d]; s += df * df; }
    s += __shfl_xor_sync(0xffffffffu, s, 1);
    s += __shfl_xor_sync(0xffffffffu, s, 2);
    s += __shfl_xor_sync(0xffffffffu, s, 4);
    if (part == 0) atomicAdd(&g_acc[2 + m], exp(-(double)s / 1024.0));
}

// ---------------- persistent GRU scan ---------------------------------------
__device__ __forceinline__ void grid_bar() {
    __threadfence();
    __syncthreads();
    if (threadIdx.x == 0) {
        unsigned g = atomicAdd(&g_gen, 0u);
        if (atomicAdd(&g_cnt, 1u) == gridDim.x - 1) {
            atomicExch(&g_cnt, 0u);
            atomicAdd(&g_gen, 1u);
        } else {
            while (atomicAdd(&g_gen, 0u) == g) { __nanosleep(64); }
        }
    }
    __syncthreads();
    __threadfence();
}

__global__ void __launch_bounds__(256, 1) gru_scan(
    const float* __restrict__ Whh, const float* __restrict__ bhh)
{
    extern __shared__ float smf[];
    float* Ws = smf;
    float* hT = smf + 24 * 1024;
    __shared__ float sbh[24];

    const int tid = threadIdx.x;
    const int j0 = blockIdx.x * 8;

    for (int e = tid; e < 24 * 1024; e += 256) {
        int c = e >> 10, k = e & 1023;
        int gate = c >> 3, jj = c & 7;
        Ws[e] = Whh[(size_t)k * T3 + gate * DCODE + j0 + jj];
    }
    if (tid < 24) {
        int gate = tid >> 3, jj = tid & 7;
        sbh[tid] = bhh[gate * DCODE + j0 + jj];
    }
    for (int e = tid; e < NB * DCODE; e += 256) hT[e] = 0.f;
    __syncthreads();

    const int b = tid & 31;
    const int jl = tid >> 5;
    const int j = j0 + jl;
    const float* wr = Ws + jl * 1024;
    const float* wz = Ws + (8 + jl) * 1024;
    const float* wn = Ws + (16 + jl) * 1024;
    const float br = sbh[jl], bz = sbh[8 + jl], bn = sbh[16 + jl];
    const float* hp = hT + b;
    const float* gxb = g_gx + (size_t)b * TSEQ * T3 + j;

    float xr = gxb[0], xz = gxb[DCODE], xn = gxb[2 * DCODE];

    for (int t = 0; t < TSEQ; t++) {
        if (t > 0) {
            grid_bar();
            const float* src = g_hG + (size_t)((t - 1) & 1) * (NB * DCODE);
            for (int e = tid * 4; e < NB * DCODE; e += 1024) {
                float4 v = __ldcg((const float4*)(src + e));
                *(float4*)(hT + e) = v;
            }
            __syncthreads();
        }
        float pxr = 0.f, pxz = 0.f, pxn = 0.f;
        if (t + 1 < TSEQ) {
            const float* gn = gxb + (size_t)(t + 1) * T3;
            pxr = gn[0]; pxz = gn[DCODE]; pxn = gn[2 * DCODE];
        }
        float ar = br, az = bz, an = bn;
        #pragma unroll 4
        for (int k = 0; k < 1024; k += 4) {
            float4 a4 = *(const float4*)(wr + k);
            float4 z4 = *(const float4*)(wz + k);
            float4 n4 = *(const float4*)(wn + k);
            float h0 = hp[(k + 0) * 32];
            float h1 = hp[(k + 1) * 32];
            float h2 = hp[(k + 2) * 32];
            float h3 = hp[(k + 3) * 32];
            ar += h0 * a4.x + h1 * a4.y + h2 * a4.z + h3 * a4.w;
            az += h0 * z4.x + h1 * z4.y + h2 * z4.z + h3 * z4.w;
            an += h0 * n4.x + h1 * n4.y + h2 * n4.z + h3 * n4.w;
        }
        float r = 1.f / (1.f + expf(-(xr + ar)));
        float z = 1.f / (1.f + expf(-(xz + az)));
        float n = tanhf(xn + r * an);
        float hprev = hT[j * 32 + b];
        float hn = (1.f - z) * n + z * hprev;
        g_ctx[((size_t)b * TSEQ + t) * DCODE + j] = hn;
        __stcg(&g_hG[(size_t)(t & 1) * (NB * DCODE) + j * 32 + b], hn);
        xr = pxr; xz = pxz; xn = pxn;
    }
}

// ---------------- init / finalize -------------------------------------------
__global__ void zero_acc() {
    if (threadIdx.x < 8) g_acc[threadIdx.x] = 0.0;
}

__global__ void finalize(float* __restrict__ out) {
    double recon = g_acc[0] / ((double)BT * (double)DIN);
    double vq    = 1.25 * g_acc[1] / ((double)BT * (double)DCODE);
    double xx = g_acc[2] / 1024.0, yy = g_acc[3] / 1024.0, xy = g_acc[4] / 1024.0;
    double mmd = xx + yy - 2.0 * xy;
    out[0] = (float)recon;
    out[1] = (float)vq;
    out[2] = (float)mmd;
    out[3] = (float)(recon + vq + 0.5 * mmd);
}

// ---------------- launch -----------------------------------------------------
extern "C" void kernel_launch(void* const* d_in, const int* in_sizes, int n_in,
                              void* d_out, int out_size) {
    const float* x       = (const float*)d_in[0];
    const float* prior   = (const float*)d_in[1];
    const float* enc_W1  = (const float*)d_in[2];
    const float* enc_b1  = (const float*)d_in[3];
    const float* ln_g    = (const float*)d_in[4];
    const float* ln_b    = (const float*)d_in[5];
    const float* enc_W2  = (const float*)d_in[6];
    const float* enc_b2  = (const float*)d_in[7];
    const float* codebook= (const float*)d_in[8];
    const float* proj_W1 = (const float*)d_in[9];
    const float* proj_b1 = (const float*)d_in[10];
    const float* proj_W2 = (const float*)d_in[11];
    const float* proj_b2 = (const float*)d_in[12];
    const float* gru_Wih = (const float*)d_in[13];
    const float* gru_Whh = (const float*)d_in[14];
    const float* gru_bih = (const float*)d_in[15];
    const float* gru_bhh = (const float*)d_in[16];
    const float* head_W  = (const float*)d_in[17];
    const float* head_b  = (const float*)d_in[18];
    float* out = (float*)d_out;

    cudaFuncSetAttribute(gru_scan, cudaFuncAttributeMaxDynamicSharedMemorySize,
                         (24 * 1024 + NB * DCODE) * (int)sizeof(float));
    cudaFuncSetAttribute(sgemm2<0>, cudaFuncAttributeMaxDynamicSharedMemorySize, SG_SMEM);
    cudaFuncSetAttribute(sgemm2<1>, cudaFuncAttributeMaxDynamicSharedMemorySize, SG_SMEM);

    zero_acc<<<1, 32>>>();

    // encoder
    sgemm2<0><<<dim3(DHID / 128, BT / 128), 256, SG_SMEM>>>(x, enc_W1, enc_b1, g_h1,
                                                            BT, DHID, DIN);
    ln_relu<<<BT, 256>>>(g_h1, ln_g, ln_b);
    sgemm2<0><<<dim3(DCODE / 128, BT / 128), 256, SG_SMEM>>>(g_h1, enc_W2, enc_b2, g_feat,
                                                             BT, DCODE, DHID);
    // VQ
    transpose_cb<<<DCODE, KCB>>>(codebook);
    cnorm_k<<<KCB, 256>>>(codebook);
    sgemm2<0><<<dim3(KCB / 128, BT / 128), 256, SG_SMEM>>>(g_feat, g_cbT, nullptr, g_S,
                                                           BT, KCB, DCODE);
    vq_kernel<<<BT, 256>>>(codebook);
    mse_kernel<<<1024, 256>>>(g_q, g_feat, (size_t)BT * DCODE, 1);

    // projector + MMD (mean over t pushed through W2)
    sgemm2<1><<<dim3(DHID / 128, BT / 128), 256, SG_SMEM>>>(g_q, proj_W1, proj_b1, g_p,
                                                            BT, DHID, DCODE);
    pm_kernel<<<BT / 256, 256>>>();
    xm_kernel<<<dim3(NB, DCODE / 256), 256>>>(proj_W2, proj_b2);
    mmd_kernel<<<dim3(NB, 3), 256>>>(prior);

    // GRU input projections + scan
    sgemm2<0><<<dim3(T3 / 128, BT / 128), 256, SG_SMEM>>>(g_q, gru_Wih, gru_bih, g_gx,
                                                          BT, T3, DCODE);
    gru_scan<<<128, 256, (24 * 1024 + NB * DCODE) * sizeof(float)>>>(gru_Whh, gru_bhh);

    // head -> recon buffer (reuse g_gx), then decoupled recon loss
    sgemm2<0><<<dim3(DIN / 128, BT / 128), 256, SG_SMEM>>>(g_ctx, head_W, head_b, g_gx,
                                                           BT, DIN, DCODE);
    mse_kernel<<<1024, 256>>>(g_gx, x, (size_t)BT * DIN, 0);

    finalize<<<1, 1>>>(out);
}